// round 4
// baseline (speedup 1.0000x reference)
#include <cuda_runtime.h>
#include <cuda_bf16.h>
#include <cstdint>
#include <math.h>

#define S_LEN 2048
#define E_DIM 1024
#define NH    16
#define DH    64

// ---------------------------------------------------------------------------
// Scratch (__device__ globals; allocation-free rule)
// ---------------------------------------------------------------------------
__device__ __align__(16) float g_q[NH * S_LEN * DH];
__device__ __align__(16) float g_k[NH * S_LEN * DH];
__device__ __align__(16) float g_v[NH * S_LEN * DH];
__device__ __align__(16) float g_ao[S_LEN * E_DIM];

// bf16 split operands (hi + lo residual)
__device__ __align__(16) __nv_bfloat16 g_xh[S_LEN * E_DIM];
__device__ __align__(16) __nv_bfloat16 g_xl[S_LEN * E_DIM];
__device__ __align__(16) __nv_bfloat16 g_wth[3 * E_DIM * E_DIM];  // [3072][1024] K-major
__device__ __align__(16) __nv_bfloat16 g_wtl[3 * E_DIM * E_DIM];
__device__ __align__(16) __nv_bfloat16 g_woth[E_DIM * E_DIM];     // [1024][1024] K-major
__device__ __align__(16) __nv_bfloat16 g_wotl[E_DIM * E_DIM];
__device__ __align__(16) __nv_bfloat16 g_aoh[S_LEN * E_DIM];
__device__ __align__(16) __nv_bfloat16 g_aol[S_LEN * E_DIM];

// ---------------------------------------------------------------------------
// Baseline-PTX tensor helpers (mma.sync / ldmatrix — valid on sm_103 target)
// ---------------------------------------------------------------------------
__device__ __forceinline__ uint32_t smem_to_u32(const void* p) {
    uint32_t a;
    asm("{ .reg .u64 t; cvta.to.shared.u64 t, %1; cvt.u32.u64 %0, t; }"
        : "=r"(a) : "l"(p));
    return a;
}

__device__ __forceinline__ void ldsm4(uint32_t* r, uint32_t addr) {
    asm volatile("ldmatrix.sync.aligned.m8n8.x4.shared.b16 {%0,%1,%2,%3}, [%4];"
        : "=r"(r[0]), "=r"(r[1]), "=r"(r[2]), "=r"(r[3]) : "r"(addr));
}

__device__ __forceinline__ void mma16816(float* c, const uint32_t* a, const uint32_t* b) {
    asm volatile(
        "mma.sync.aligned.m16n8k16.row.col.f32.bf16.bf16.f32 "
        "{%0,%1,%2,%3}, {%4,%5,%6,%7}, {%8,%9}, {%0,%1,%2,%3};"
        : "+f"(c[0]), "+f"(c[1]), "+f"(c[2]), "+f"(c[3])
        : "r"(a[0]), "r"(a[1]), "r"(a[2]), "r"(a[3]), "r"(b[0]), "r"(b[1]));
}

// ---------------------------------------------------------------------------
// Conversion kernels: fp32 -> bf16 hi + lo residual
// ---------------------------------------------------------------------------
__device__ __forceinline__ void split1(float v, __nv_bfloat16& h, __nv_bfloat16& l) {
    h = __float2bfloat16(v);
    l = __float2bfloat16(v - __bfloat162float(h));
}

__global__ __launch_bounds__(256) void conv_split_x(const float* __restrict__ in) {
    int i = (blockIdx.x * 256 + threadIdx.x) * 4;
    float4 v = *(const float4*)(in + i);
    __nv_bfloat16 h0, h1, h2, h3, l0, l1, l2, l3;
    split1(v.x, h0, l0); split1(v.y, h1, l1);
    split1(v.z, h2, l2); split1(v.w, h3, l3);
    __nv_bfloat162 a; a.x = h0; a.y = h1;
    __nv_bfloat162 b; b.x = h2; b.y = h3;
    *(__nv_bfloat162*)(g_xh + i) = a; *(__nv_bfloat162*)(g_xh + i + 2) = b;
    a.x = l0; a.y = l1; b.x = l2; b.y = l3;
    *(__nv_bfloat162*)(g_xl + i) = a; *(__nv_bfloat162*)(g_xl + i + 2) = b;
}

__global__ __launch_bounds__(256) void conv_split_ao() {
    int i = (blockIdx.x * 256 + threadIdx.x) * 4;
    float4 v = *(const float4*)(g_ao + i);
    __nv_bfloat16 h0, h1, h2, h3, l0, l1, l2, l3;
    split1(v.x, h0, l0); split1(v.y, h1, l1);
    split1(v.z, h2, l2); split1(v.w, h3, l3);
    __nv_bfloat162 a; a.x = h0; a.y = h1;
    __nv_bfloat162 b; b.x = h2; b.y = h3;
    *(__nv_bfloat162*)(g_aoh + i) = a; *(__nv_bfloat162*)(g_aoh + i + 2) = b;
    a.x = l0; a.y = l1; b.x = l2; b.y = l3;
    *(__nv_bfloat162*)(g_aol + i) = a; *(__nv_bfloat162*)(g_aol + i + 2) = b;
}

// W[h][e][d] -> Wt[(z*1024 + h*64 + d)][e]  (K-major rows for B operand)
__global__ __launch_bounds__(256) void wqkv_transpose(
    const float* __restrict__ Wq, const float* __restrict__ Wk,
    const float* __restrict__ Wv)
{
    __shared__ float s[64][65];
    const int z = blockIdx.z, h = blockIdx.y, e0 = blockIdx.x * 64;
    const float* W = (z == 0 ? Wq : z == 1 ? Wk : Wv) + (size_t)h * E_DIM * DH;
    const int tid = threadIdx.x;
    #pragma unroll
    for (int i = 0; i < 16; i++) {
        int idx = tid + i * 256;
        int e = idx >> 6, d = idx & 63;
        s[d][e] = W[(size_t)(e0 + e) * DH + d];
    }
    __syncthreads();
    const int nb = z * 1024 + h * 64;
    #pragma unroll
    for (int i = 0; i < 16; i++) {
        int idx = tid + i * 256;
        int d = idx >> 6, e = idx & 63;
        __nv_bfloat16 hh, ll;
        split1(s[d][e], hh, ll);
        g_wth[(size_t)(nb + d) * E_DIM + e0 + e] = hh;
        g_wtl[(size_t)(nb + d) * E_DIM + e0 + e] = ll;
    }
}

// Wo[f][e] -> Wot[e][f]
__global__ __launch_bounds__(256) void wo_transpose(const float* __restrict__ Wo) {
    __shared__ float s[64][65];
    const int f0 = blockIdx.x * 64, e0 = blockIdx.y * 64;
    const int tid = threadIdx.x;
    #pragma unroll
    for (int i = 0; i < 16; i++) {
        int idx = tid + i * 256;
        int fl = idx >> 6, el = idx & 63;
        s[el][fl] = Wo[(size_t)(f0 + fl) * E_DIM + e0 + el];
    }
    __syncthreads();
    #pragma unroll
    for (int i = 0; i < 16; i++) {
        int idx = tid + i * 256;
        int el = idx >> 6, fl = idx & 63;
        __nv_bfloat16 hh, ll;
        split1(s[el][fl], hh, ll);
        g_woth[(size_t)(e0 + el) * E_DIM + f0 + fl] = hh;
        g_wotl[(size_t)(e0 + el) * E_DIM + f0 + fl] = ll;
    }
}

// ---------------------------------------------------------------------------
// mma.sync bf16-split GEMM: C[M=2048, N] = A[M,1024] * B^T[N,1024] (+bias)
// mode 0: A = x (hi/lo), B = Wqkv_t, N=3072 -> scatter to g_q/g_k/g_v (+bq/bk/bv)
// mode 1: A = ao (hi/lo), B = Wot,   N=1024 -> out (+bo)
// BM=128, BN=128, BK=32; 8 warps (2x4), warp tile 64x32 of m16n8k16.
// ---------------------------------------------------------------------------
#define PAD_K 40   // row stride in bf16 (80 bytes -> conflict-free ldmatrix)

__global__ __launch_bounds__(256, 2) void gemm_mma_kernel(
    int mode, const float* __restrict__ bias0, const float* __restrict__ bias1,
    const float* __restrict__ bias2, float* __restrict__ out)
{
    __shared__ __nv_bfloat16 sA[2][128][PAD_K];   // [hi/lo][row][k]
    __shared__ __nv_bfloat16 sB[2][128][PAD_K];

    const int tid = threadIdx.x;
    const int wid = tid >> 5, lane = tid & 31;
    const int wm = wid >> 2, wn = wid & 3;      // 2 x 4 warp grid
    const int m0 = blockIdx.x * 128, n0 = blockIdx.y * 128;

    const __nv_bfloat16* Ah = mode ? g_aoh : g_xh;
    const __nv_bfloat16* Al = mode ? g_aol : g_xl;
    const __nv_bfloat16* Bh = mode ? g_woth : g_wth;
    const __nv_bfloat16* Bl = mode ? g_wotl : g_wtl;

    const uint32_t saH = smem_to_u32(&sA[0][0][0]);
    const uint32_t saL = smem_to_u32(&sA[1][0][0]);
    const uint32_t sbH = smem_to_u32(&sB[0][0][0]);
    const uint32_t sbL = smem_to_u32(&sB[1][0][0]);

    float c[4][4][4];
    #pragma unroll
    for (int mi = 0; mi < 4; mi++)
        #pragma unroll
        for (int ni = 0; ni < 4; ni++)
            #pragma unroll
            for (int e = 0; e < 4; e++) c[mi][ni][e] = 0.f;

    // precomputed fragment smem offsets (bytes)
    const uint32_t aRow = wm * 64 + (lane & 15);
    const uint32_t aColHalf = (lane >> 4) << 4;       // 0 or 16 bytes
    const uint32_t bGrp = lane >> 3, bRin = lane & 7;
    const uint32_t bRowBase = wn * 32 + ((bGrp >> 1) << 3) + bRin;
    const uint32_t bColHalf = (bGrp & 1) << 4;        // 0 or 16 bytes

    for (int kc = 0; kc < E_DIM / 32; kc++) {
        const int k0 = kc * 32;
        __syncthreads();
        // load 4 tiles of 128x32 bf16 (8 uint4 per thread)
        #pragma unroll
        for (int t = 0; t < 4; t++) {
            const __nv_bfloat16* src =
                (t == 0 ? Ah + (size_t)m0 * E_DIM : t == 1 ? Al + (size_t)m0 * E_DIM :
                 t == 2 ? Bh + (size_t)n0 * E_DIM : Bl + (size_t)n0 * E_DIM) + k0;
            __nv_bfloat16* dst = (t == 0 ? &sA[0][0][0] : t == 1 ? &sA[1][0][0] :
                                  t == 2 ? &sB[0][0][0] : &sB[1][0][0]);
            #pragma unroll
            for (int i = 0; i < 2; i++) {
                int idx = tid + i * 256;
                int row = idx >> 2, q = idx & 3;
                uint4 v = *(const uint4*)(src + (size_t)row * E_DIM + q * 8);
                *(uint4*)(dst + row * PAD_K + q * 8) = v;
            }
        }
        __syncthreads();

        #pragma unroll
        for (int ks = 0; ks < 2; ks++) {
            const uint32_t kbyte = ks * 32;
            uint32_t ah[4][4], al[4][4], bh[4][2], bl[4][2];
            #pragma unroll
            for (int mi = 0; mi < 4; mi++) {
                uint32_t off = (aRow + mi * 16) * (PAD_K * 2) + kbyte + aColHalf;
                ldsm4(ah[mi], saH + off);
                ldsm4(al[mi], saL + off);
            }
            #pragma unroll
            for (int half = 0; half < 2; half++) {
                uint32_t off = (bRowBase + half * 16) * (PAD_K * 2) + kbyte + bColHalf;
                ldsm4(&bh[half * 2][0], sbH + off);
                ldsm4(&bl[half * 2][0], sbL + off);
            }
            #pragma unroll
            for (int mi = 0; mi < 4; mi++)
                #pragma unroll
                for (int ni = 0; ni < 4; ni++) {
                    mma16816(c[mi][ni], ah[mi], bh[ni]);
                    mma16816(c[mi][ni], ah[mi], bl[ni]);
                    mma16816(c[mi][ni], al[mi], bh[ni]);
                }
        }
    }

    // Epilogue: bias + scatter. C frag: c0,c1 at (r, n),(r, n+1); c2,c3 at (r+8).
    const int rBase = m0 + wm * 64 + (lane >> 2);
    const int nBase = n0 + wn * 32 + (lane & 3) * 2;
    #pragma unroll
    for (int mi = 0; mi < 4; mi++) {
        #pragma unroll
        for (int ni = 0; ni < 4; ni++) {
            int n = nBase + ni * 8;
            #pragma unroll
            for (int half = 0; half < 2; half++) {
                int row = rBase + mi * 16 + half * 8;
                float v0 = c[mi][ni][half * 2 + 0];
                float v1 = c[mi][ni][half * 2 + 1];
                if (mode == 0) {
                    const int z = n >> 10;
                    const float* bias = z == 0 ? bias0 : z == 1 ? bias1 : bias2;
                    float* dst = z == 0 ? g_q : z == 1 ? g_k : g_v;
                    const int h = (n >> 6) & 15, d = n & 63, bi = n & 1023;
                    float2 o;
                    o.x = v0 + __ldg(&bias[bi + 0]);
                    o.y = v1 + __ldg(&bias[bi + 1]);
                    *(float2*)&dst[((size_t)h * S_LEN + row) * DH + d] = o;
                } else {
                    float2 o;
                    o.x = v0 + __ldg(&bias0[n + 0]);
                    o.y = v1 + __ldg(&bias0[n + 1]);
                    *(float2*)&out[(size_t)row * E_DIM + n] = o;
                }
            }
        }
    }
}

// ---------------------------------------------------------------------------
// Causal flash attention (SIMT fp32, unchanged)
// ---------------------------------------------------------------------------
__global__ __launch_bounds__(256) void attn_kernel()
{
    extern __shared__ float sm[];
    float* Qs = sm;
    float* Ks = sm + 4096;
    float* Vs = sm + 8192;
    float* Ps = sm + 12288;

    const int h  = blockIdx.y;
    const int i0 = blockIdx.x;
    const float* Q = g_q + (size_t)h * S_LEN * DH;
    const float* K = g_k + (size_t)h * S_LEN * DH;
    const float* V = g_v + (size_t)h * S_LEN * DH;

    const int tid = threadIdx.x;
    const int ty = tid >> 4, tx = tid & 15;

    #pragma unroll
    for (int r = 0; r < 4; r++) {
        int idx4 = tid + 256 * r;
        int m = idx4 >> 4, dq = idx4 & 15;
        float4 v = *(const float4*)&Q[(size_t)(i0 * 64 + m) * DH + dq * 4];
        Qs[(dq * 4 + 0) * 64 + m] = v.x;
        Qs[(dq * 4 + 1) * 64 + m] = v.y;
        Qs[(dq * 4 + 2) * 64 + m] = v.z;
        Qs[(dq * 4 + 3) * 64 + m] = v.w;
    }

    float o[4][4], m_i[4], l_i[4];
    #pragma unroll
    for (int i = 0; i < 4; i++) {
        m_i[i] = -1e30f; l_i[i] = 0.f;
        #pragma unroll
        for (int j = 0; j < 4; j++) o[i][j] = 0.f;
    }

    for (int jt = 0; jt <= i0; jt++) {
        __syncthreads();
        #pragma unroll
        for (int r = 0; r < 4; r++) {
            int idx4 = tid + 256 * r;
            int kk = idx4 >> 4, dq = idx4 & 15;
            float4 kv = *(const float4*)&K[(size_t)(jt * 64 + kk) * DH + dq * 4];
            Ks[(dq * 4 + 0) * 64 + kk] = kv.x;
            Ks[(dq * 4 + 1) * 64 + kk] = kv.y;
            Ks[(dq * 4 + 2) * 64 + kk] = kv.z;
            Ks[(dq * 4 + 3) * 64 + kk] = kv.w;
            *(float4*)&Vs[kk * 64 + dq * 4] =
                *(const float4*)&V[(size_t)(jt * 64 + kk) * DH + dq * 4];
        }
        __syncthreads();

        float sc[4][4];
        #pragma unroll
        for (int i = 0; i < 4; i++)
            #pragma unroll
            for (int j = 0; j < 4; j++) sc[i][j] = 0.f;

        #pragma unroll 4
        for (int d = 0; d < 64; d++) {
            float a[4];
            #pragma unroll
            for (int i = 0; i < 4; i++) a[i] = Qs[d * 64 + ty * 4 + i];
            float4 b4 = *(const float4*)&Ks[d * 64 + tx * 4];
            float b[4] = {b4.x, b4.y, b4.z, b4.w};
            #pragma unroll
            for (int i = 0; i < 4; i++)
                #pragma unroll
                for (int j = 0; j < 4; j++) sc[i][j] += a[i] * b[j];
        }

        const float scale = 0.125f;
        if (jt == i0) {
            #pragma unroll
            for (int i = 0; i < 4; i++) {
                int row = ty * 4 + i;
                #pragma unroll
                for (int j = 0; j < 4; j++) {
                    int col = tx * 4 + j;
                    sc[i][j] = (col <= row) ? sc[i][j] * scale : -1e30f;
                }
            }
        } else {
            #pragma unroll
            for (int i = 0; i < 4; i++)
                #pragma unroll
                for (int j = 0; j < 4; j++) sc[i][j] *= scale;
        }

        #pragma unroll
        for (int i = 0; i < 4; i++) {
            float mr = fmaxf(fmaxf(sc[i][0], sc[i][1]), fmaxf(sc[i][2], sc[i][3]));
            #pragma unroll
            for (int off = 8; off >= 1; off >>= 1)
                mr = fmaxf(mr, __shfl_xor_sync(0xffffffffu, mr, off));
            float mnew = fmaxf(m_i[i], mr);
            float f = __expf(m_i[i] - mnew);
            float rs = 0.f;
            #pragma unroll
            for (int j = 0; j < 4; j++) {
                sc[i][j] = __expf(sc[i][j] - mnew);
                rs += sc[i][j];
            }
            #pragma unroll
            for (int off = 8; off >= 1; off >>= 1)
                rs += __shfl_xor_sync(0xffffffffu, rs, off);
            l_i[i] = l_i[i] * f + rs;
            m_i[i] = mnew;
            #pragma unroll
            for (int j = 0; j < 4; j++) o[i][j] *= f;
            #pragma unroll
            for (int j = 0; j < 4; j++)
                Ps[(tx * 4 + j) * 65 + ty * 4 + i] = sc[i][j];
        }
        __syncthreads();

        #pragma unroll 4
        for (int kk = 0; kk < 64; kk++) {
            float a[4];
            #pragma unroll
            for (int i = 0; i < 4; i++) a[i] = Ps[kk * 65 + ty * 4 + i];
            float4 b4 = *(const float4*)&Vs[kk * 64 + tx * 4];
            float b[4] = {b4.x, b4.y, b4.z, b4.w};
            #pragma unroll
            for (int i = 0; i < 4; i++)
                #pragma unroll
                for (int j = 0; j < 4; j++) o[i][j] += a[i] * b[j];
        }
    }

    #pragma unroll
    for (int i = 0; i < 4; i++) {
        float inv = 1.f / l_i[i];
        int row = i0 * 64 + ty * 4 + i;
        float4 ov;
        ov.x = o[i][0] * inv; ov.y = o[i][1] * inv;
        ov.z = o[i][2] * inv; ov.w = o[i][3] * inv;
        *(float4*)&g_ao[(size_t)row * E_DIM + h * DH + tx * 4] = ov;
    }
}

// ---------------------------------------------------------------------------
extern "C" void kernel_launch(void* const* d_in, const int* in_sizes, int n_in,
                              void* d_out, int out_size)
{
    const float* x  = (const float*)d_in[0];
    const float* Wq = (const float*)d_in[1];
    const float* bq = (const float*)d_in[2];
    const float* Wk = (const float*)d_in[3];
    const float* bk = (const float*)d_in[4];
    const float* Wv = (const float*)d_in[5];
    const float* bv = (const float*)d_in[6];
    const float* Wo = (const float*)d_in[7];
    const float* bo = (const float*)d_in[8];
    float* out = (float*)d_out;

    (void)in_sizes; (void)n_in; (void)out_size;

    cudaFuncSetAttribute(attn_kernel,
                         cudaFuncAttributeMaxDynamicSharedMemorySize, 65792);

    conv_split_x<<<2048, 256>>>(x);
    wqkv_transpose<<<dim3(16, 16, 3), 256>>>(Wq, Wk, Wv);
    wo_transpose<<<dim3(16, 16), 256>>>(Wo);
    gemm_mma_kernel<<<dim3(16, 24), 256>>>(0, bq, bk, bv, nullptr);
    attn_kernel<<<dim3(S_LEN / 64, NH), 256, 65792>>>();
    conv_split_ao<<<2048, 256>>>();
    gemm_mma_kernel<<<dim3(16, 8), 256>>>(1, bo, nullptr, nullptr, out);
}

// round 9
// speedup vs baseline: 3.3440x; 3.3440x over previous
#include <cuda_runtime.h>
#include <cuda_bf16.h>
#include <cstdint>
#include <math.h>

#define S_LEN 2048
#define E_DIM 1024
#define NH    16
#define DH    64

// ---------------------------------------------------------------------------
// Scratch (__device__ globals; allocation-free rule)
// ---------------------------------------------------------------------------
// q/k/v stored as bf16 hi+lo, layout [h][s][d]; q pre-scaled by 0.125 (1/sqrt(64))
__device__ __align__(16) __nv_bfloat16 g_qh[NH * S_LEN * DH];
__device__ __align__(16) __nv_bfloat16 g_ql[NH * S_LEN * DH];
__device__ __align__(16) __nv_bfloat16 g_kh[NH * S_LEN * DH];
__device__ __align__(16) __nv_bfloat16 g_kl[NH * S_LEN * DH];
__device__ __align__(16) __nv_bfloat16 g_vh[NH * S_LEN * DH];
__device__ __align__(16) __nv_bfloat16 g_vl[NH * S_LEN * DH];

__device__ __align__(16) __nv_bfloat16 g_xh[S_LEN * E_DIM];
__device__ __align__(16) __nv_bfloat16 g_xl[S_LEN * E_DIM];
__device__ __align__(16) __nv_bfloat16 g_wth[3 * E_DIM * E_DIM];  // [3072][1024] K-major
__device__ __align__(16) __nv_bfloat16 g_wtl[3 * E_DIM * E_DIM];
__device__ __align__(16) __nv_bfloat16 g_woth[E_DIM * E_DIM];     // [1024][1024] K-major
__device__ __align__(16) __nv_bfloat16 g_wotl[E_DIM * E_DIM];
__device__ __align__(16) __nv_bfloat16 g_aoh[S_LEN * E_DIM];      // attn out, concat layout
__device__ __align__(16) __nv_bfloat16 g_aol[S_LEN * E_DIM];

// ---------------------------------------------------------------------------
// Baseline-PTX helpers (all valid on plain sm_103 target)
// ---------------------------------------------------------------------------
__device__ __forceinline__ uint32_t smem_to_u32(const void* p) {
    uint32_t a;
    asm("{ .reg .u64 t; cvta.to.shared.u64 t, %1; cvt.u32.u64 %0, t; }"
        : "=r"(a) : "l"(p));
    return a;
}

__device__ __forceinline__ void ldsm4(uint32_t* r, uint32_t addr) {
    asm volatile("ldmatrix.sync.aligned.m8n8.x4.shared.b16 {%0,%1,%2,%3}, [%4];"
        : "=r"(r[0]), "=r"(r[1]), "=r"(r[2]), "=r"(r[3]) : "r"(addr));
}
__device__ __forceinline__ void ldsm4t(uint32_t* r, uint32_t addr) {
    asm volatile("ldmatrix.sync.aligned.m8n8.x4.trans.shared.b16 {%0,%1,%2,%3}, [%4];"
        : "=r"(r[0]), "=r"(r[1]), "=r"(r[2]), "=r"(r[3]) : "r"(addr));
}

__device__ __forceinline__ void mma16816(float* c, const uint32_t* a, const uint32_t* b) {
    asm volatile(
        "mma.sync.aligned.m16n8k16.row.col.f32.bf16.bf16.f32 "
        "{%0,%1,%2,%3}, {%4,%5,%6,%7}, {%8,%9}, {%0,%1,%2,%3};"
        : "+f"(c[0]), "+f"(c[1]), "+f"(c[2]), "+f"(c[3])
        : "r"(a[0]), "r"(a[1]), "r"(a[2]), "r"(a[3]), "r"(b[0]), "r"(b[1]));
}

__device__ __forceinline__ void cpasync16(uint32_t saddr, const void* gaddr) {
    asm volatile("cp.async.cg.shared.global [%0], [%1], 16;"
        :: "r"(saddr), "l"(gaddr) : "memory");
}
#define CP_COMMIT() asm volatile("cp.async.commit_group;" ::: "memory")
#define CP_WAIT(n)  asm volatile("cp.async.wait_group %0;" :: "n"(n) : "memory")

__device__ __forceinline__ void split1(float v, __nv_bfloat16& h, __nv_bfloat16& l) {
    h = __float2bfloat16(v);
    l = __float2bfloat16(v - __bfloat162float(h));
}
// pack (a,b) -> bf16x2 hi + bf16x2 lo residuals
__device__ __forceinline__ void packsplit2(float a, float b, uint32_t& hi, uint32_t& lo) {
    __nv_bfloat162 h, l;
    h.x = __float2bfloat16(a); h.y = __float2bfloat16(b);
    l.x = __float2bfloat16(a - __bfloat162float(h.x));
    l.y = __float2bfloat16(b - __bfloat162float(h.y));
    hi = *(uint32_t*)&h; lo = *(uint32_t*)&l;
}
__device__ __forceinline__ void splitstore2(float a, float b,
                                            __nv_bfloat16* ph, __nv_bfloat16* pl) {
    __nv_bfloat162 h, l;
    h.x = __float2bfloat16(a); h.y = __float2bfloat16(b);
    l.x = __float2bfloat16(a - __bfloat162float(h.x));
    l.y = __float2bfloat16(b - __bfloat162float(h.y));
    *(__nv_bfloat162*)ph = h; *(__nv_bfloat162*)pl = l;
}

// ---------------------------------------------------------------------------
// Conversion / transpose kernels
// ---------------------------------------------------------------------------
__global__ __launch_bounds__(256) void conv_split_x(const float* __restrict__ in) {
    int i = (blockIdx.x * 256 + threadIdx.x) * 4;
    float4 v = *(const float4*)(in + i);
    splitstore2(v.x, v.y, g_xh + i, g_xl + i);
    splitstore2(v.z, v.w, g_xh + i + 2, g_xl + i + 2);
}

// W[h][e][d] -> Wt[(z*1024 + h*64 + d)][e]  (K-major rows for B operand)
__global__ __launch_bounds__(256) void wqkv_transpose(
    const float* __restrict__ Wq, const float* __restrict__ Wk,
    const float* __restrict__ Wv)
{
    __shared__ float s[64][65];
    const int z = blockIdx.z, h = blockIdx.y, e0 = blockIdx.x * 64;
    const float* W = (z == 0 ? Wq : z == 1 ? Wk : Wv) + (size_t)h * E_DIM * DH;
    const int tid = threadIdx.x;
    #pragma unroll
    for (int i = 0; i < 16; i++) {
        int idx = tid + i * 256;
        int e = idx >> 6, d = idx & 63;
        s[d][e] = W[(size_t)(e0 + e) * DH + d];
    }
    __syncthreads();
    const int nb = z * 1024 + h * 64;
    #pragma unroll
    for (int i = 0; i < 16; i++) {
        int idx = tid + i * 256;
        int d = idx >> 6, e = idx & 63;
        __nv_bfloat16 hh, ll;
        split1(s[d][e], hh, ll);
        g_wth[(size_t)(nb + d) * E_DIM + e0 + e] = hh;
        g_wtl[(size_t)(nb + d) * E_DIM + e0 + e] = ll;
    }
}

// Wo[f][e] -> Wot[e][f]
__global__ __launch_bounds__(256) void wo_transpose(const float* __restrict__ Wo) {
    __shared__ float s[64][65];
    const int f0 = blockIdx.x * 64, e0 = blockIdx.y * 64;
    const int tid = threadIdx.x;
    #pragma unroll
    for (int i = 0; i < 16; i++) {
        int idx = tid + i * 256;
        int fl = idx >> 6, el = idx & 63;
        s[el][fl] = Wo[(size_t)(f0 + fl) * E_DIM + e0 + el];
    }
    __syncthreads();
    #pragma unroll
    for (int i = 0; i < 16; i++) {
        int idx = tid + i * 256;
        int el = idx >> 6, fl = idx & 63;
        __nv_bfloat16 hh, ll;
        split1(s[el][fl], hh, ll);
        g_woth[(size_t)(e0 + el) * E_DIM + f0 + fl] = hh;
        g_wotl[(size_t)(e0 + el) * E_DIM + f0 + fl] = ll;
    }
}

// ---------------------------------------------------------------------------
// cp.async double-buffered mma.sync bf16-split GEMM.
// mode 0: A = x, B = Wqkv_t (N=3072) -> g_q/k/v bf16 hi/lo (+bias; q scaled 0.125)
// mode 1: A = ao, B = Wot (N=1024)   -> out fp32 (+bo)
// BM=128, BN=128, BK=32; 8 warps; warp tile 64x32.
// Dyn smem: 2 stages x 4 tiles x [128][40] bf16 = 81920 B.
// ---------------------------------------------------------------------------
#define GPAD 40
#define GEMM_SMEM_BYTES (2 * 4 * 128 * GPAD * 2)

__global__ __launch_bounds__(256, 2) void gemm_mma_kernel(
    int mode, const float* __restrict__ bias0, const float* __restrict__ bias1,
    const float* __restrict__ bias2, float* __restrict__ out)
{
    extern __shared__ __nv_bfloat16 gs[];
    const uint32_t sb = smem_to_u32(gs);
    const int tid = threadIdx.x;
    const int wid = tid >> 5, lane = tid & 31;
    const int wm = wid >> 2, wn = wid & 3;
    const int m0 = blockIdx.x * 128, n0 = blockIdx.y * 128;

    const __nv_bfloat16* bp[4];
    bp[0] = (mode ? g_aoh : g_xh) + (size_t)m0 * E_DIM;
    bp[1] = (mode ? g_aol : g_xl) + (size_t)m0 * E_DIM;
    bp[2] = (mode ? g_woth : g_wth) + (size_t)n0 * E_DIM;
    bp[3] = (mode ? g_wotl : g_wtl) + (size_t)n0 * E_DIM;

    // issue loads for chunk kc into stage s
    auto issue = [&](int s, int kc) {
        const int k0 = kc * 32;
        #pragma unroll
        for (int t = 0; t < 4; t++) {
            const __nv_bfloat16* src = bp[t] + k0;
            const uint32_t db = sb + (s * 20480 + t * 5120) * 2;
            #pragma unroll
            for (int i = 0; i < 2; i++) {
                int idx = tid + i * 256;
                int row = idx >> 2, q = idx & 3;
                cpasync16(db + (row * GPAD + q * 8) * 2,
                          src + (size_t)row * E_DIM + q * 8);
            }
        }
    };

    float c[4][4][4];
    #pragma unroll
    for (int mi = 0; mi < 4; mi++)
        #pragma unroll
        for (int ni = 0; ni < 4; ni++)
            #pragma unroll
            for (int e = 0; e < 4; e++) c[mi][ni][e] = 0.f;

    const uint32_t aRow = wm * 64 + (lane & 15);
    const uint32_t aColHalf = (lane >> 4) << 4;       // bytes
    const uint32_t bGrp = lane >> 3, bRin = lane & 7;
    const uint32_t bRowBase = wn * 32 + ((bGrp >> 1) << 3) + bRin;
    const uint32_t bColHalf = (bGrp & 1) << 4;        // bytes

    issue(0, 0); CP_COMMIT();

    for (int kc = 0; kc < 32; kc++) {
        const int buf = kc & 1;
        if (kc < 31) { issue(buf ^ 1, kc + 1); CP_COMMIT(); CP_WAIT(1); }
        else         { CP_WAIT(0); }
        __syncthreads();

        const uint32_t saH = sb + (buf * 20480 +     0) * 2;
        const uint32_t saL = sb + (buf * 20480 +  5120) * 2;
        const uint32_t sbH = sb + (buf * 20480 + 10240) * 2;
        const uint32_t sbL = sb + (buf * 20480 + 15360) * 2;

        #pragma unroll
        for (int ks = 0; ks < 2; ks++) {
            const uint32_t kbyte = ks * 32;
            uint32_t ah[4][4], al[4][4], bh[4][2], bl[4][2];
            #pragma unroll
            for (int mi = 0; mi < 4; mi++) {
                uint32_t off = (aRow + mi * 16) * (GPAD * 2) + kbyte + aColHalf;
                ldsm4(ah[mi], saH + off);
                ldsm4(al[mi], saL + off);
            }
            #pragma unroll
            for (int half = 0; half < 2; half++) {
                uint32_t off = (bRowBase + half * 16) * (GPAD * 2) + kbyte + bColHalf;
                ldsm4(&bh[half * 2][0], sbH + off);
                ldsm4(&bl[half * 2][0], sbL + off);
            }
            #pragma unroll
            for (int mi = 0; mi < 4; mi++)
                #pragma unroll
                for (int ni = 0; ni < 4; ni++) {
                    mma16816(c[mi][ni], ah[mi], bh[ni]);
                    mma16816(c[mi][ni], ah[mi], bl[ni]);
                    mma16816(c[mi][ni], al[mi], bh[ni]);
                }
        }
        __syncthreads();
    }

    // Epilogue
    const int rBase = m0 + wm * 64 + (lane >> 2);
    const int nBase = n0 + wn * 32 + (lane & 3) * 2;
    #pragma unroll
    for (int mi = 0; mi < 4; mi++) {
        #pragma unroll
        for (int ni = 0; ni < 4; ni++) {
            int n = nBase + ni * 8;
            #pragma unroll
            for (int half = 0; half < 2; half++) {
                int row = rBase + mi * 16 + half * 8;
                float v0 = c[mi][ni][half * 2 + 0];
                float v1 = c[mi][ni][half * 2 + 1];
                if (mode == 0) {
                    const int z = n >> 10;
                    const float* bias = z == 0 ? bias0 : z == 1 ? bias1 : bias2;
                    __nv_bfloat16* dh = z == 0 ? g_qh : z == 1 ? g_kh : g_vh;
                    __nv_bfloat16* dl = z == 0 ? g_ql : z == 1 ? g_kl : g_vl;
                    const int h = (n >> 6) & 15, d = n & 63, bi = n & 1023;
                    const float scl = (z == 0) ? 0.125f : 1.0f;
                    float a = (v0 + __ldg(&bias[bi + 0])) * scl;
                    float b = (v1 + __ldg(&bias[bi + 1])) * scl;
                    size_t o = ((size_t)h * S_LEN + row) * DH + d;
                    splitstore2(a, b, dh + o, dl + o);
                } else {
                    float2 o;
                    o.x = v0 + __ldg(&bias0[n + 0]);
                    o.y = v1 + __ldg(&bias0[n + 1]);
                    *(float2*)&out[(size_t)row * E_DIM + n] = o;
                }
            }
        }
    }
}

// ---------------------------------------------------------------------------
// Tensor-core causal flash attention.
// Block = 128 threads (4 warps), each warp 16 of the 64 Q rows.
// Q*K^T and P*V via 3-term bf16-split mma.sync; online softmax in C-fragments.
// Dyn smem: Qh/Ql + 2-stage {Kh,Kl,Vh,Vl}, rows padded to 72 bf16.
// ---------------------------------------------------------------------------
#define APAD 72
#define ATN_SMEM_BYTES ((2 + 8) * 64 * APAD * 2)   // 92160

__global__ __launch_bounds__(128) void attn_mma_kernel()
{
    extern __shared__ __nv_bfloat16 as2[];
    const uint32_t sbq = smem_to_u32(as2);
    const int tid = threadIdx.x, lane = tid & 31, w = tid >> 5;
    const int i0 = (int)gridDim.x - 1 - (int)blockIdx.x;  // heavy tiles first
    const int h = blockIdx.y;

    const __nv_bfloat16* Qh = g_qh + ((size_t)h * S_LEN + i0 * 64) * DH;
    const __nv_bfloat16* Ql = g_ql + ((size_t)h * S_LEN + i0 * 64) * DH;

    // smem byte offsets
    const uint32_t sQh = sbq;
    const uint32_t sQl = sbq + 9216;
    // stage s: base sbq + 18432 + s*36864; tiles Kh,Kl,Vh,Vl at +0,9216,18432,27648

    auto load_kv = [&](int s, int jt) {
        const size_t gofs = ((size_t)h * S_LEN + jt * 64) * DH;
        const __nv_bfloat16* src[4] = { g_kh + gofs, g_kl + gofs,
                                        g_vh + gofs, g_vl + gofs };
        const uint32_t stb = sbq + 18432 + s * 36864;
        #pragma unroll
        for (int t = 0; t < 4; t++) {
            const uint32_t db = stb + t * 9216;
            #pragma unroll
            for (int i = 0; i < 4; i++) {
                int idx = tid + i * 128;
                int row = idx >> 3, q = idx & 7;
                cpasync16(db + (row * APAD + q * 8) * 2, src[t] + row * 64 + q * 8);
            }
        }
    };

    // issue Q + first K/V
    #pragma unroll
    for (int i = 0; i < 4; i++) {
        int idx = tid + i * 128;
        int row = idx >> 3, q = idx & 7;
        cpasync16(sQh + (row * APAD + q * 8) * 2, Qh + row * 64 + q * 8);
        cpasync16(sQl + (row * APAD + q * 8) * 2, Ql + row * 64 + q * 8);
    }
    load_kv(0, 0);
    CP_COMMIT();

    float m0 = -1e30f, m1 = -1e30f, l0 = 0.f, l1 = 0.f;
    float oc[8][4];
    #pragma unroll
    for (int ni = 0; ni < 8; ni++)
        #pragma unroll
        for (int e = 0; e < 4; e++) oc[ni][e] = 0.f;

    uint32_t aQh[4][4], aQl[4][4];
    const int grp = lane >> 3, rin = lane & 7;
    const int rowq = lane >> 2, colq = (lane & 3) * 2;

    for (int jt = 0; jt <= i0; jt++) {
        const int buf = jt & 1;
        if (jt < i0) { load_kv(buf ^ 1, jt + 1); CP_COMMIT(); CP_WAIT(1); }
        else         { CP_WAIT(0); }
        __syncthreads();

        if (jt == 0) {
            const uint32_t qrow = w * 16 + (lane & 15);
            const uint32_t qcol = (lane >> 4) << 3;
            #pragma unroll
            for (int ks = 0; ks < 4; ks++) {
                uint32_t off = (qrow * APAD + ks * 16 + qcol) * 2;
                ldsm4(aQh[ks], sQh + off);
                ldsm4(aQl[ks], sQl + off);
            }
        }

        const uint32_t stb = sbq + 18432 + buf * 36864;
        const uint32_t sKh = stb, sKl = stb + 9216;
        const uint32_t sVh = stb + 18432, sVl = stb + 27648;

        // ---- S = Q K^T (scores pre-scaled via q) ----
        float sc[8][4];
        #pragma unroll
        for (int ni = 0; ni < 8; ni++)
            #pragma unroll
            for (int e = 0; e < 4; e++) sc[ni][e] = 0.f;

        #pragma unroll
        for (int ks = 0; ks < 4; ks++) {
            #pragma unroll
            for (int g = 0; g < 4; g++) {
                uint32_t kh[4], kl[4];
                uint32_t off = ((g * 16 + ((grp >> 1) << 3) + rin) * APAD
                                + ks * 16 + (grp & 1) * 8) * 2;
                ldsm4(kh, sKh + off);
                ldsm4(kl, sKl + off);
                mma16816(sc[2 * g],     aQh[ks], kh);
                mma16816(sc[2 * g],     aQh[ks], kl);
                mma16816(sc[2 * g],     aQl[ks], kh);
                mma16816(sc[2 * g + 1], aQh[ks], kh + 2);
                mma16816(sc[2 * g + 1], aQh[ks], kl + 2);
                mma16816(sc[2 * g + 1], aQl[ks], kh + 2);
            }
        }

        // ---- causal mask (diagonal tile only) ----
        if (jt == i0) {
            const int rowL0 = w * 16 + rowq, rowL1 = rowL0 + 8;
            #pragma unroll
            for (int ni = 0; ni < 8; ni++) {
                int colL = ni * 8 + colq;
                if (colL     > rowL0) sc[ni][0] = -1e30f;
                if (colL + 1 > rowL0) sc[ni][1] = -1e30f;
                if (colL     > rowL1) sc[ni][2] = -1e30f;
                if (colL + 1 > rowL1) sc[ni][3] = -1e30f;
            }
        }

        // ---- online softmax ----
        float t0 = -1e30f, t1 = -1e30f;
        #pragma unroll
        for (int ni = 0; ni < 8; ni++) {
            t0 = fmaxf(t0, fmaxf(sc[ni][0], sc[ni][1]));
            t1 = fmaxf(t1, fmaxf(sc[ni][2], sc[ni][3]));
        }
        t0 = fmaxf(t0, __shfl_xor_sync(0xffffffffu, t0, 1));
        t0 = fmaxf(t0, __shfl_xor_sync(0xffffffffu, t0, 2));
        t1 = fmaxf(t1, __shfl_xor_sync(0xffffffffu, t1, 1));
        t1 = fmaxf(t1, __shfl_xor_sync(0xffffffffu, t1, 2));
        const float m0n = fmaxf(m0, t0), m1n = fmaxf(m1, t1);
        const float f0 = __expf(m0 - m0n), f1 = __expf(m1 - m1n);

        float rs0 = 0.f, rs1 = 0.f;
        #pragma unroll
        for (int ni = 0; ni < 8; ni++) {
            sc[ni][0] = __expf(sc[ni][0] - m0n); rs0 += sc[ni][0];
            sc[ni][1] = __expf(sc[ni][1] - m0n); rs0 += sc[ni][1];
            sc[ni][2] = __expf(sc[ni][2] - m1n); rs1 += sc[ni][2];
            sc[ni][3] = __expf(sc[ni][3] - m1n); rs1 += sc[ni][3];
        }
        rs0 += __shfl_xor_sync(0xffffffffu, rs0, 1);
        rs0 += __shfl_xor_sync(0xffffffffu, rs0, 2);
        rs1 += __shfl_xor_sync(0xffffffffu, rs1, 1);
        rs1 += __shfl_xor_sync(0xffffffffu, rs1, 2);
        l0 = l0 * f0 + rs0; l1 = l1 * f1 + rs1;
        m0 = m0n; m1 = m1n;
        #pragma unroll
        for (int ni = 0; ni < 8; ni++) {
            oc[ni][0] *= f0; oc[ni][1] *= f0;
            oc[ni][2] *= f1; oc[ni][3] *= f1;
        }

        // ---- pack P fragments (hi/lo) ----
        uint32_t aPh[4][4], aPl[4][4];
        #pragma unroll
        for (int ks = 0; ks < 4; ks++) {
            const int ta = 2 * ks, tb = 2 * ks + 1;
            packsplit2(sc[ta][0], sc[ta][1], aPh[ks][0], aPl[ks][0]);
            packsplit2(sc[ta][2], sc[ta][3], aPh[ks][1], aPl[ks][1]);
            packsplit2(sc[tb][0], sc[tb][1], aPh[ks][2], aPl[ks][2]);
            packsplit2(sc[tb][2], sc[tb][3], aPh[ks][3], aPl[ks][3]);
        }

        // ---- O += P V ----
        #pragma unroll
        for (int ks = 0; ks < 4; ks++) {
            #pragma unroll
            for (int g = 0; g < 4; g++) {
                uint32_t vh[4], vl[4];
                uint32_t off = ((ks * 16 + ((grp & 1) << 3) + rin) * APAD
                                + g * 16 + ((grp >> 1) << 3)) * 2;
                ldsm4t(vh, sVh + off);
                ldsm4t(vl, sVl + off);
                mma16816(oc[2 * g],     aPh[ks], vh);
                mma16816(oc[2 * g],     aPh[ks], vl);
                mma16816(oc[2 * g],     aPl[ks], vh);
                mma16816(oc[2 * g + 1], aPh[ks], vh + 2);
                mma16816(oc[2 * g + 1], aPh[ks], vl + 2);
                mma16816(oc[2 * g + 1], aPl[ks], vh + 2);
            }
        }
        __syncthreads();
    }

    // ---- epilogue: normalize, split, store concat layout ----
    const float inv0 = 1.f / l0, inv1 = 1.f / l1;
    const int row0 = i0 * 64 + w * 16 + rowq;
    const int colb = h * 64 + colq;
    #pragma unroll
    for (int ni = 0; ni < 8; ni++) {
        const int col = colb + ni * 8;
        size_t o0 = (size_t)row0 * E_DIM + col;
        size_t o1 = (size_t)(row0 + 8) * E_DIM + col;
        splitstore2(oc[ni][0] * inv0, oc[ni][1] * inv0, g_aoh + o0, g_aol + o0);
        splitstore2(oc[ni][2] * inv1, oc[ni][3] * inv1, g_aoh + o1, g_aol + o1);
    }
}

// ---------------------------------------------------------------------------
extern "C" void kernel_launch(void* const* d_in, const int* in_sizes, int n_in,
                              void* d_out, int out_size)
{
    const float* x  = (const float*)d_in[0];
    const float* Wq = (const float*)d_in[1];
    const float* bq = (const float*)d_in[2];
    const float* Wk = (const float*)d_in[3];
    const float* bk = (const float*)d_in[4];
    const float* Wv = (const float*)d_in[5];
    const float* bv = (const float*)d_in[6];
    const float* Wo = (const float*)d_in[7];
    const float* bo = (const float*)d_in[8];
    float* out = (float*)d_out;

    (void)in_sizes; (void)n_in; (void)out_size;

    cudaFuncSetAttribute(gemm_mma_kernel,
                         cudaFuncAttributeMaxDynamicSharedMemorySize, GEMM_SMEM_BYTES);
    cudaFuncSetAttribute(attn_mma_kernel,
                         cudaFuncAttributeMaxDynamicSharedMemorySize, ATN_SMEM_BYTES);

    conv_split_x<<<2048, 256>>>(x);
    wqkv_transpose<<<dim3(16, 16, 3), 256>>>(Wq, Wk, Wv);
    wo_transpose<<<dim3(16, 16), 256>>>(Wo);
    gemm_mma_kernel<<<dim3(16, 24), 256, GEMM_SMEM_BYTES>>>(0, bq, bk, bv, nullptr);
    attn_mma_kernel<<<dim3(S_LEN / 64, NH), 128, ATN_SMEM_BYTES>>>();
    gemm_mma_kernel<<<dim3(16, 8), 256, GEMM_SMEM_BYTES>>>(1, bo, nullptr, nullptr, out);
}